// round 5
// baseline (speedup 1.0000x reference)
#include <cuda_runtime.h>
#include <cuda_bf16.h>
#include <math.h>
#include <stdint.h>

#define B_ROWS 16384
#define D_DIM  1024
#define R_DIM  64
#define E_NUM  4
#define L_NUM  2
#define N1     256   // E * R

// ---------------------------------------------------------------------------
// Device scratch
// ---------------------------------------------------------------------------
__device__ __nv_bfloat16 g_W1hi[L_NUM * N1 * D_DIM];   // [L][n=e*64+r][k=d]
__device__ __nv_bfloat16 g_W1lo[L_NUM * N1 * D_DIM];
__device__ __nv_bfloat16 g_W2hi[L_NUM * D_DIM * N1];   // [L][n=d][k=e*64+r]
__device__ __nv_bfloat16 g_W2lo[L_NUM * D_DIM * N1];
__device__ __nv_bfloat16 g_Xhi[B_ROWS * D_DIM];
__device__ __nv_bfloat16 g_Xlo[B_ROWS * D_DIM];
__device__ __nv_bfloat16 g_Zhi[B_ROWS * N1];
__device__ __nv_bfloat16 g_Zlo[B_ROWS * N1];
__device__ float g_H   [B_ROWS * N1];
__device__ float g_Xl  [B_ROWS * D_DIM];
__device__ float g_Gate[B_ROWS * E_NUM];

// ---------------------------------------------------------------------------
// Helpers
// ---------------------------------------------------------------------------
__device__ __forceinline__ uint32_t smem_u32(const void* p) {
    uint32_t a;
    asm("{ .reg .u64 t; cvta.to.shared.u64 t, %1; cvt.u32.u64 %0, t; }"
        : "=r"(a) : "l"(p));
    return a;
}

__device__ __forceinline__ void bf16_split(float v, __nv_bfloat16& h, __nv_bfloat16& l) {
    h = __float2bfloat16(v);
    l = __float2bfloat16(v - __bfloat162float(h));
}

#define CP_ASYNC16(dst, src) \
    asm volatile("cp.async.cg.shared.global [%0], [%1], 16;" :: "r"(dst), "l"(src))
#define CP_COMMIT() asm volatile("cp.async.commit_group;" ::: "memory")
#define CP_WAIT1()  asm volatile("cp.async.wait_group 1;" ::: "memory")

#define LDSM_X4(r0, r1, r2, r3, addr) \
    asm volatile("ldmatrix.sync.aligned.m8n8.x4.shared.b16 {%0,%1,%2,%3}, [%4];" \
        : "=r"(r0), "=r"(r1), "=r"(r2), "=r"(r3) : "r"(addr))

#define MMA_BF16(d, a, b0, b1) \
    asm volatile("mma.sync.aligned.m16n8k16.row.col.f32.bf16.bf16.f32 " \
        "{%0,%1,%2,%3}, {%4,%5,%6,%7}, {%8,%9}, {%0,%1,%2,%3};" \
        : "+f"((d)[0]), "+f"((d)[1]), "+f"((d)[2]), "+f"((d)[3]) \
        : "r"((a)[0]), "r"((a)[1]), "r"((a)[2]), "r"((a)[3]), "r"(b0), "r"(b1))

// ---------------------------------------------------------------------------
// Weight repack + bf16 hi/lo split
// ---------------------------------------------------------------------------
__global__ void repack_kernel(const float* __restrict__ U, const float* __restrict__ V) {
    int idx = blockIdx.x * blockDim.x + threadIdx.x;
    const int per = N1 * D_DIM;
    if (idx >= L_NUM * per) return;
    int i   = idx / per;
    int rem = idx - i * per;
    {   // W1[n][k] = V[i, e=n>>6, d=k, r=n&63]
        int n = rem / D_DIM, k = rem - (rem / D_DIM) * D_DIM;
        float v = V[(((size_t)i * E_NUM + (n >> 6)) * D_DIM + k) * R_DIM + (n & 63)];
        bf16_split(v, g_W1hi[idx], g_W1lo[idx]);
    }
    {   // W2[d][k2] = U[i, e=k2>>6, d, r=k2&63]
        int d = rem / N1, k2 = rem - (rem / N1) * N1;
        float u = U[(((size_t)i * E_NUM + (k2 >> 6)) * D_DIM + d) * R_DIM + (k2 & 63)];
        bf16_split(u, g_W2hi[idx], g_W2lo[idx]);
    }
}

__global__ void split_x_kernel(const float* __restrict__ x) {
    int i = (blockIdx.x * 256 + threadIdx.x) * 4;
    float4 v = *(const float4*)(x + i);
    __nv_bfloat162 h01, h23, l01, l23;
    bf16_split(v.x, h01.x, l01.x);
    bf16_split(v.y, h01.y, l01.y);
    bf16_split(v.z, h23.x, l23.x);
    bf16_split(v.w, h23.y, l23.y);
    *(__nv_bfloat162*)(g_Xhi + i)     = h01;
    *(__nv_bfloat162*)(g_Xhi + i + 2) = h23;
    *(__nv_bfloat162*)(g_Xlo + i)     = l01;
    *(__nv_bfloat162*)(g_Xlo + i + 2) = l23;
}

// ---------------------------------------------------------------------------
// Gate kernel: warp-per-row logits + softmax -> g_Gate[b][4]
// ---------------------------------------------------------------------------
__global__ void __launch_bounds__(256)
gate_kernel(const float* __restrict__ X, const float* __restrict__ gateW,
            float* __restrict__ gate)
{
    __shared__ float sG[E_NUM * D_DIM];
    const int tid = threadIdx.x;
    #pragma unroll
    for (int i = tid * 4; i < E_NUM * D_DIM; i += 1024)
        *(float4*)(sG + i) = *(const float4*)(gateW + i);
    __syncthreads();

    const int warp = tid >> 5, lane = tid & 31;
    const int b = blockIdx.x * 8 + warp;
    const float* xr = X + (size_t)b * D_DIM;

    float a0 = 0.f, a1 = 0.f, a2 = 0.f, a3 = 0.f;
    #pragma unroll
    for (int j = 0; j < 8; j++) {
        const int off = lane * 4 + j * 128;
        float4 xv = *(const float4*)(xr + off);
        float4 g0 = *(const float4*)(sG + 0 * D_DIM + off);
        float4 g1 = *(const float4*)(sG + 1 * D_DIM + off);
        float4 g2 = *(const float4*)(sG + 2 * D_DIM + off);
        float4 g3 = *(const float4*)(sG + 3 * D_DIM + off);
        a0 += xv.x * g0.x + xv.y * g0.y + xv.z * g0.z + xv.w * g0.w;
        a1 += xv.x * g1.x + xv.y * g1.y + xv.z * g1.z + xv.w * g1.w;
        a2 += xv.x * g2.x + xv.y * g2.y + xv.z * g2.z + xv.w * g2.w;
        a3 += xv.x * g3.x + xv.y * g3.y + xv.z * g3.z + xv.w * g3.w;
    }
    #pragma unroll
    for (int o = 16; o > 0; o >>= 1) {
        a0 += __shfl_xor_sync(0xffffffffu, a0, o);
        a1 += __shfl_xor_sync(0xffffffffu, a1, o);
        a2 += __shfl_xor_sync(0xffffffffu, a2, o);
        a3 += __shfl_xor_sync(0xffffffffu, a3, o);
    }
    float mx = fmaxf(fmaxf(a0, a1), fmaxf(a2, a3));
    float e0 = expf(a0 - mx), e1 = expf(a1 - mx), e2 = expf(a2 - mx), e3 = expf(a3 - mx);
    float inv = 1.0f / (e0 + e1 + e2 + e3);
    if (lane < 4) {
        float v = (lane == 0) ? e0 : (lane == 1) ? e1 : (lane == 2) ? e2 : e3;
        gate[b * 4 + lane] = v * inv;
    }
}

// ---------------------------------------------------------------------------
// Middle v2: register-resident C. Thread tid owns C row n=tid (64 regs).
// ---------------------------------------------------------------------------
__global__ void __launch_bounds__(256)
middle_kernel2(const float* __restrict__ C, const float* __restrict__ gate,
               const float* __restrict__ H,
               __nv_bfloat16* __restrict__ Zhi, __nv_bfloat16* __restrict__ Zlo)
{
    __shared__ float sH[8][N1];
    const int tid = threadIdx.x;
    const int b0  = blockIdx.x * 8;
    const int e   = tid >> 6;

    float Creg[64];
    {
        const float* crow = C + (size_t)tid * 64;
        #pragma unroll
        for (int q = 0; q < 64; q += 4) {
            float4 v = *(const float4*)(crow + q);
            Creg[q + 0] = v.x; Creg[q + 1] = v.y;
            Creg[q + 2] = v.z; Creg[q + 3] = v.w;
        }
    }
    {
        const int row = tid >> 5;
        const int c   = (tid & 31) * 8;
        *(float4*)(&sH[row][c])     = *(const float4*)(H + (size_t)(b0 + row) * N1 + c);
        *(float4*)(&sH[row][c + 4]) = *(const float4*)(H + (size_t)(b0 + row) * N1 + c + 4);
    }
    __syncthreads();

    #pragma unroll
    for (int r = 0; r < 8; r++) {
        const float* hseg = &sH[r][e * 64];
        float acc = 0.0f;
        #pragma unroll
        for (int q = 0; q < 64; q++)
            acc = fmaf(Creg[q], hseg[q], acc);
        const float g = gate[(b0 + r) * 4 + e];
        const float z = g * tanhf(acc);
        __nv_bfloat16 zh, zl;
        bf16_split(z, zh, zl);
        Zhi[(size_t)(b0 + r) * N1 + tid] = zh;
        Zlo[(size_t)(b0 + r) * N1 + tid] = zl;
    }
}

// ---------------------------------------------------------------------------
// Stage loader for GEMM
// ---------------------------------------------------------------------------
template<int KDIM>
__device__ __forceinline__ void load_stage(
    uint32_t sbase,
    const __nv_bfloat16* __restrict__ Ah, const __nv_bfloat16* __restrict__ Al,
    const __nv_bfloat16* __restrict__ Bh, const __nv_bfloat16* __restrict__ Bl,
    int k0, int tid)
{
    #pragma unroll
    for (int h = 0; h < 2; h++) {
        int c   = tid + h * 256;       // 0..511
        int row = c >> 2;
        int kb  = c & 3;
        size_t   go = (size_t)row * KDIM + k0 + kb * 8;
        uint32_t so = (uint32_t)(kb * 2048 + row * 16);
        CP_ASYNC16(sbase +          so, Ah + go);
        CP_ASYNC16(sbase +  8192u + so, Al + go);
        CP_ASYNC16(sbase + 16384u + so, Bh + go);
        CP_ASYNC16(sbase + 24576u + so, Bl + go);
    }
}

// ---------------------------------------------------------------------------
// bf16 split mma GEMM: BM=128, BN=128, BK=32, 8 warps (4m x 2n).
// 3-product schedule re-phased so Bhi/Blo fragments never coexist
// (peak live regs ~115 < 128 -> no spills at 2 CTAs/SM).
// MODE 0: out = tanh(A@B)
// MODE 1: out = xl + x0*(A@B + bias)
// MODE 2: out = x0*(1 + A@B + bias), + bf16 hi/lo split of out
// ---------------------------------------------------------------------------
template<int MODE, int KDIM>
__global__ void __launch_bounds__(256, 2)
mma_gemm(const __nv_bfloat16* __restrict__ Ahi, const __nv_bfloat16* __restrict__ Alo,
         const __nv_bfloat16* __restrict__ Bhi, const __nv_bfloat16* __restrict__ Blo,
         const float* __restrict__ x0, const float* __restrict__ xl,
         const float* __restrict__ bias, float* __restrict__ out,
         __nv_bfloat16* __restrict__ outhi, __nv_bfloat16* __restrict__ outlo,
         int Nstride)
{
    constexpr int BK = 32, NK = KDIM / BK, NST = 3;
    extern __shared__ char smem[];
    const uint32_t sbase = smem_u32(smem);

    const int tid  = threadIdx.x;
    const int wid  = tid >> 5;
    const int lane = tid & 31;
    const int wm   = wid & 3;
    const int wn   = wid >> 2;

    const __nv_bfloat16* Ah = Ahi + (size_t)blockIdx.y * 128 * KDIM;
    const __nv_bfloat16* Al = Alo + (size_t)blockIdx.y * 128 * KDIM;
    const __nv_bfloat16* Bh = Bhi + (size_t)blockIdx.x * 128 * KDIM;
    const __nv_bfloat16* Bl = Blo + (size_t)blockIdx.x * 128 * KDIM;

    float acc[2][8][4];
    #pragma unroll
    for (int a = 0; a < 2; a++)
        #pragma unroll
        for (int b = 0; b < 8; b++)
            #pragma unroll
            for (int c = 0; c < 4; c++) acc[a][b][c] = 0.0f;

    load_stage<KDIM>(sbase,          Ah, Al, Bh, Bl, 0,  tid); CP_COMMIT();
    load_stage<KDIM>(sbase + 32768u, Ah, Al, Bh, Bl, BK, tid); CP_COMMIT();

    const uint32_t arow16 = (uint32_t)((wm * 32 + (lane & 15)) * 16);
    const uint32_t asel   = (uint32_t)(lane >> 4) * 2048u;
    const uint32_t brow16 = (uint32_t)((wn * 64 + (lane & 7) + ((lane >> 4) << 3)) * 16);
    const uint32_t bsel   = (uint32_t)((lane >> 3) & 1) * 2048u;

    for (int i = 0; i < NK; i++) {
        CP_WAIT1();
        __syncthreads();
        if (i + 2 < NK)
            load_stage<KDIM>(sbase + (uint32_t)((i + 2) % NST) * 32768u,
                             Ah, Al, Bh, Bl, (i + 2) * BK, tid);
        CP_COMMIT();

        const uint32_t st = sbase + (uint32_t)(i % NST) * 32768u;
        #pragma unroll
        for (int kk = 0; kk < 2; kk++) {
            const uint32_t kboff = (uint32_t)kk * 4096u;
            uint32_t ah[2][4], al[2][4], bb[4][4];

            // --- Phase 1: B = Bhi, products Ah*Bh and Al*Bh ---
            #pragma unroll
            for (int g = 0; g < 4; g++) {
                uint32_t bd = st + 16384u + kboff + bsel + brow16 + (uint32_t)g * 256u;
                LDSM_X4(bb[g][0], bb[g][1], bb[g][2], bb[g][3], bd);
            }
            #pragma unroll
            for (int mt = 0; mt < 2; mt++) {
                uint32_t ad = st + kboff + asel + arow16 + (uint32_t)mt * 256u;
                LDSM_X4(ah[mt][0], ah[mt][1], ah[mt][2], ah[mt][3], ad);
            }
            #pragma unroll
            for (int mt = 0; mt < 2; mt++)
                #pragma unroll
                for (int nt = 0; nt < 8; nt++) {
                    const int g = nt >> 1, hh = (nt & 1) * 2;
                    MMA_BF16(acc[mt][nt], ah[mt], bb[g][hh], bb[g][hh + 1]);
                }
            #pragma unroll
            for (int mt = 0; mt < 2; mt++) {
                uint32_t ad = st + kboff + asel + arow16 + (uint32_t)mt * 256u;
                LDSM_X4(al[mt][0], al[mt][1], al[mt][2], al[mt][3], ad + 8192u);
            }
            #pragma unroll
            for (int mt = 0; mt < 2; mt++)
                #pragma unroll
                for (int nt = 0; nt < 8; nt++) {
                    const int g = nt >> 1, hh = (nt & 1) * 2;
                    MMA_BF16(acc[mt][nt], al[mt], bb[g][hh], bb[g][hh + 1]);
                }

            // --- Phase 2: B = Blo (reuse bb regs), product Ah*Bl ---
            #pragma unroll
            for (int g = 0; g < 4; g++) {
                uint32_t bd = st + 16384u + kboff + bsel + brow16 + (uint32_t)g * 256u;
                LDSM_X4(bb[g][0], bb[g][1], bb[g][2], bb[g][3], bd + 8192u);
            }
            #pragma unroll
            for (int mt = 0; mt < 2; mt++)
                #pragma unroll
                for (int nt = 0; nt < 8; nt++) {
                    const int g = nt >> 1, hh = (nt & 1) * 2;
                    MMA_BF16(acc[mt][nt], ah[mt], bb[g][hh], bb[g][hh + 1]);
                }
        }
    }

    const int r0    = lane >> 2;
    const int cpair = (lane & 3) * 2;
    #pragma unroll
    for (int mt = 0; mt < 2; mt++)
        #pragma unroll
        for (int nt = 0; nt < 8; nt++) {
            const int row = blockIdx.y * 128 + wm * 32 + mt * 16 + r0;
            const int col = blockIdx.x * 128 + wn * 64 + nt * 8 + cpair;
            #pragma unroll
            for (int h = 0; h < 2; h++) {
                const int rr = row + h * 8;
                const float v0 = acc[mt][nt][h * 2 + 0];
                const float v1 = acc[mt][nt][h * 2 + 1];
                const size_t o = (size_t)rr * Nstride + col;
                if (MODE == 0) {
                    float2 ov;
                    ov.x = tanhf(v0);
                    ov.y = tanhf(v1);
                    *(float2*)(out + o) = ov;
                } else if (MODE == 1) {
                    const float2 bv = *(const float2*)(bias + col);
                    const float2 xv = *(const float2*)(x0 + o);
                    const float2 lv = *(const float2*)(xl + o);
                    float2 ov;
                    ov.x = fmaf(xv.x, v0 + bv.x, lv.x);
                    ov.y = fmaf(xv.y, v1 + bv.y, lv.y);
                    *(float2*)(out + o) = ov;
                } else {
                    const float2 bv = *(const float2*)(bias + col);
                    const float2 xv = *(const float2*)(x0 + o);
                    float2 ov;
                    ov.x = xv.x * (1.0f + v0 + bv.x);
                    ov.y = xv.y * (1.0f + v1 + bv.y);
                    *(float2*)(out + o) = ov;
                    __nv_bfloat162 hv, lv2;
                    bf16_split(ov.x, hv.x, lv2.x);
                    bf16_split(ov.y, hv.y, lv2.y);
                    *(__nv_bfloat162*)(outhi + o) = hv;
                    *(__nv_bfloat162*)(outlo + o) = lv2;
                }
            }
        }
}

// ---------------------------------------------------------------------------
extern "C" void kernel_launch(void* const* d_in, const int* in_sizes, int n_in,
                              void* d_out, int out_size)
{
    const float* x     = (const float*)d_in[0];
    const float* U     = (const float*)d_in[1];
    const float* V     = (const float*)d_in[2];
    const float* C     = (const float*)d_in[3];
    const float* bias  = (const float*)d_in[4];
    const float* gateW = (const float*)d_in[5];
    float* out = (float*)d_out;

    __nv_bfloat16 *w1h, *w1l, *w2h, *w2l, *xh, *xlobf, *zh, *zl;
    float *hbuf, *xlbuf, *gbuf;
    cudaGetSymbolAddress((void**)&w1h,   g_W1hi);
    cudaGetSymbolAddress((void**)&w1l,   g_W1lo);
    cudaGetSymbolAddress((void**)&w2h,   g_W2hi);
    cudaGetSymbolAddress((void**)&w2l,   g_W2lo);
    cudaGetSymbolAddress((void**)&xh,    g_Xhi);
    cudaGetSymbolAddress((void**)&xlobf, g_Xlo);
    cudaGetSymbolAddress((void**)&zh,    g_Zhi);
    cudaGetSymbolAddress((void**)&zl,    g_Zlo);
    cudaGetSymbolAddress((void**)&hbuf,  g_H);
    cudaGetSymbolAddress((void**)&xlbuf, g_Xl);
    cudaGetSymbolAddress((void**)&gbuf,  g_Gate);

    const int GEMM_SMEM = 3 * 32768;
    cudaFuncSetAttribute(mma_gemm<0, 1024>, cudaFuncAttributeMaxDynamicSharedMemorySize, GEMM_SMEM);
    cudaFuncSetAttribute(mma_gemm<1, 256>,  cudaFuncAttributeMaxDynamicSharedMemorySize, GEMM_SMEM);
    cudaFuncSetAttribute(mma_gemm<2, 256>,  cudaFuncAttributeMaxDynamicSharedMemorySize, GEMM_SMEM);

    repack_kernel<<<(L_NUM * N1 * D_DIM + 255) / 256, 256>>>(U, V);
    split_x_kernel<<<B_ROWS * D_DIM / 4 / 256, 256>>>(x);

    for (int i = 0; i < L_NUM; i++) {
        const float* xin = (i == 0) ? x : xlbuf;
        const size_t woff = (size_t)i * N1 * D_DIM;
        const float* Cl = C + (size_t)i * E_NUM * R_DIM * R_DIM;

        // GEMM1: H = tanh(X @ W1^T)   [16384 x 256], K = 1024
        mma_gemm<0, 1024><<<dim3(2, B_ROWS / 128), 256, GEMM_SMEM>>>(
            xh, xlobf, w1h + woff, w1l + woff,
            nullptr, nullptr, nullptr, hbuf, nullptr, nullptr, N1);

        gate_kernel<<<B_ROWS / 8, 256>>>(xin, gateW, gbuf);

        middle_kernel2<<<B_ROWS / 8, 256>>>(Cl, gbuf, hbuf, zh, zl);

        // GEMM2: out = xl + x0*(Z @ W2^T + bias)  [16384 x 1024], K = 256
        if (i == 0) {
            mma_gemm<2, 256><<<dim3(8, B_ROWS / 128), 256, GEMM_SMEM>>>(
                zh, zl, w2h + woff, w2l + woff,
                x, nullptr, bias, xlbuf, xh, xlobf, D_DIM);
        } else {
            mma_gemm<1, 256><<<dim3(8, B_ROWS / 128), 256, GEMM_SMEM>>>(
                zh, zl, w2h + woff, w2l + woff,
                x, xin, bias + (size_t)i * D_DIM, out, nullptr, nullptr, D_DIM);
        }
    }
}

// round 6
// speedup vs baseline: 1.2632x; 1.2632x over previous
#include <cuda_runtime.h>
#include <cuda_fp16.h>
#include <math.h>
#include <stdint.h>

#define B_ROWS 16384
#define D_DIM  1024
#define R_DIM  64
#define E_NUM  4
#define L_NUM  2
#define N1     256   // E * R

// ---------------------------------------------------------------------------
// Device scratch
// ---------------------------------------------------------------------------
__device__ __half g_W1h[L_NUM * N1 * D_DIM];   // [L][n=e*64+r][k=d]  fp16(V)
__device__ __half g_W2h[L_NUM * D_DIM * N1];   // [L][n=d][k=e*64+r]  fp16(U)
__device__ __half g_Xhi[B_ROWS * D_DIM];
__device__ __half g_Xlo[B_ROWS * D_DIM];
__device__ __half g_Zhi[B_ROWS * N1];
__device__ __half g_Zlo[B_ROWS * N1];
__device__ float g_H   [B_ROWS * N1];
__device__ float g_Xl  [B_ROWS * D_DIM];
__device__ float g_Gate[B_ROWS * E_NUM];

// ---------------------------------------------------------------------------
// Helpers
// ---------------------------------------------------------------------------
__device__ __forceinline__ uint32_t smem_u32(const void* p) {
    uint32_t a;
    asm("{ .reg .u64 t; cvta.to.shared.u64 t, %1; cvt.u32.u64 %0, t; }"
        : "=r"(a) : "l"(p));
    return a;
}

__device__ __forceinline__ void fp16_split(float v, __half& h, __half& l) {
    h = __float2half_rn(v);
    l = __float2half_rn(v - __half2float(h));
}

#define CP_ASYNC16(dst, src) \
    asm volatile("cp.async.cg.shared.global [%0], [%1], 16;" :: "r"(dst), "l"(src))
#define CP_COMMIT() asm volatile("cp.async.commit_group;" ::: "memory")
#define CP_WAIT1()  asm volatile("cp.async.wait_group 1;" ::: "memory")

#define LDSM_X4(r0, r1, r2, r3, addr) \
    asm volatile("ldmatrix.sync.aligned.m8n8.x4.shared.b16 {%0,%1,%2,%3}, [%4];" \
        : "=r"(r0), "=r"(r1), "=r"(r2), "=r"(r3) : "r"(addr))

#define MMA_F16(d, a, b0, b1) \
    asm volatile("mma.sync.aligned.m16n8k16.row.col.f32.f16.f16.f32 " \
        "{%0,%1,%2,%3}, {%4,%5,%6,%7}, {%8,%9}, {%0,%1,%2,%3};" \
        : "+f"((d)[0]), "+f"((d)[1]), "+f"((d)[2]), "+f"((d)[3]) \
        : "r"((a)[0]), "r"((a)[1]), "r"((a)[2]), "r"((a)[3]), "r"(b0), "r"(b1))

// ---------------------------------------------------------------------------
// Weight repack (fp16 hi only)
// ---------------------------------------------------------------------------
__global__ void repack_kernel(const float* __restrict__ U, const float* __restrict__ V) {
    int idx = blockIdx.x * blockDim.x + threadIdx.x;
    const int per = N1 * D_DIM;
    if (idx >= L_NUM * per) return;
    int i   = idx / per;
    int rem = idx - i * per;
    {   // W1[n][k] = V[i, e=n>>6, d=k, r=n&63]
        int n = rem / D_DIM, k = rem - (rem / D_DIM) * D_DIM;
        float v = V[(((size_t)i * E_NUM + (n >> 6)) * D_DIM + k) * R_DIM + (n & 63)];
        g_W1h[idx] = __float2half_rn(v);
    }
    {   // W2[d][k2] = U[i, e=k2>>6, d, r=k2&63]
        int d = rem / N1, k2 = rem - (rem / N1) * N1;
        float u = U[(((size_t)i * E_NUM + (k2 >> 6)) * D_DIM + d) * R_DIM + (k2 & 63)];
        g_W2h[(size_t)i * D_DIM * N1 + rem] = __float2half_rn(u);
    }
}

__global__ void split_x_kernel(const float* __restrict__ x) {
    int i = (blockIdx.x * 256 + threadIdx.x) * 4;
    float4 v = *(const float4*)(x + i);
    __half2 h01, h23, l01, l23;
    fp16_split(v.x, h01.x, l01.x);
    fp16_split(v.y, h01.y, l01.y);
    fp16_split(v.z, h23.x, l23.x);
    fp16_split(v.w, h23.y, l23.y);
    *(__half2*)(g_Xhi + i)     = h01;
    *(__half2*)(g_Xhi + i + 2) = h23;
    *(__half2*)(g_Xlo + i)     = l01;
    *(__half2*)(g_Xlo + i + 2) = l23;
}

// ---------------------------------------------------------------------------
// Gate kernel: warp-per-row logits + softmax -> g_Gate[b][4]
// ---------------------------------------------------------------------------
__global__ void __launch_bounds__(256)
gate_kernel(const float* __restrict__ X, const float* __restrict__ gateW,
            float* __restrict__ gate)
{
    __shared__ float sG[E_NUM * D_DIM];
    const int tid = threadIdx.x;
    #pragma unroll
    for (int i = tid * 4; i < E_NUM * D_DIM; i += 1024)
        *(float4*)(sG + i) = *(const float4*)(gateW + i);
    __syncthreads();

    const int warp = tid >> 5, lane = tid & 31;
    const int b = blockIdx.x * 8 + warp;
    const float* xr = X + (size_t)b * D_DIM;

    float a0 = 0.f, a1 = 0.f, a2 = 0.f, a3 = 0.f;
    #pragma unroll
    for (int j = 0; j < 8; j++) {
        const int off = lane * 4 + j * 128;
        float4 xv = *(const float4*)(xr + off);
        float4 g0 = *(const float4*)(sG + 0 * D_DIM + off);
        float4 g1 = *(const float4*)(sG + 1 * D_DIM + off);
        float4 g2 = *(const float4*)(sG + 2 * D_DIM + off);
        float4 g3 = *(const float4*)(sG + 3 * D_DIM + off);
        a0 += xv.x * g0.x + xv.y * g0.y + xv.z * g0.z + xv.w * g0.w;
        a1 += xv.x * g1.x + xv.y * g1.y + xv.z * g1.z + xv.w * g1.w;
        a2 += xv.x * g2.x + xv.y * g2.y + xv.z * g2.z + xv.w * g2.w;
        a3 += xv.x * g3.x + xv.y * g3.y + xv.z * g3.z + xv.w * g3.w;
    }
    #pragma unroll
    for (int o = 16; o > 0; o >>= 1) {
        a0 += __shfl_xor_sync(0xffffffffu, a0, o);
        a1 += __shfl_xor_sync(0xffffffffu, a1, o);
        a2 += __shfl_xor_sync(0xffffffffu, a2, o);
        a3 += __shfl_xor_sync(0xffffffffu, a3, o);
    }
    float mx = fmaxf(fmaxf(a0, a1), fmaxf(a2, a3));
    float e0 = expf(a0 - mx), e1 = expf(a1 - mx), e2 = expf(a2 - mx), e3 = expf(a3 - mx);
    float inv = 1.0f / (e0 + e1 + e2 + e3);
    if (lane < 4) {
        float v = (lane == 0) ? e0 : (lane == 1) ? e1 : (lane == 2) ? e2 : e3;
        gate[b * 4 + lane] = v * inv;
    }
}

// ---------------------------------------------------------------------------
// Middle v2: register-resident C. Thread tid owns C row n=tid (64 regs).
// ---------------------------------------------------------------------------
__global__ void __launch_bounds__(256)
middle_kernel2(const float* __restrict__ C, const float* __restrict__ gate,
               const float* __restrict__ H,
               __half* __restrict__ Zhi, __half* __restrict__ Zlo)
{
    __shared__ float sH[8][N1];
    const int tid = threadIdx.x;
    const int b0  = blockIdx.x * 8;
    const int e   = tid >> 6;

    float Creg[64];
    {
        const float* crow = C + (size_t)tid * 64;
        #pragma unroll
        for (int q = 0; q < 64; q += 4) {
            float4 v = *(const float4*)(crow + q);
            Creg[q + 0] = v.x; Creg[q + 1] = v.y;
            Creg[q + 2] = v.z; Creg[q + 3] = v.w;
        }
    }
    {
        const int row = tid >> 5;
        const int c   = (tid & 31) * 8;
        *(float4*)(&sH[row][c])     = *(const float4*)(H + (size_t)(b0 + row) * N1 + c);
        *(float4*)(&sH[row][c + 4]) = *(const float4*)(H + (size_t)(b0 + row) * N1 + c + 4);
    }
    __syncthreads();

    #pragma unroll
    for (int r = 0; r < 8; r++) {
        const float* hseg = &sH[r][e * 64];
        float acc = 0.0f;
        #pragma unroll
        for (int q = 0; q < 64; q++)
            acc = fmaf(Creg[q], hseg[q], acc);
        const float g = gate[(b0 + r) * 4 + e];
        const float z = g * tanhf(acc);
        __half zh, zl;
        fp16_split(z, zh, zl);
        Zhi[(size_t)(b0 + r) * N1 + tid] = zh;
        Zlo[(size_t)(b0 + r) * N1 + tid] = zl;
    }
}

// ---------------------------------------------------------------------------
// Stage loader: 3 arrays (Ahi, Alo, Bhi), each 128 rows x 32 k (fp16) = 8KB.
// Panel layout: k-chunk kb (8 k) -> 128 rows x 16B at offset kb*2048 + row*16.
// ---------------------------------------------------------------------------
template<int KDIM>
__device__ __forceinline__ void load_stage(
    uint32_t sbase,
    const __half* __restrict__ Ah, const __half* __restrict__ Al,
    const __half* __restrict__ Bh, int k0, int tid)
{
    #pragma unroll
    for (int h = 0; h < 2; h++) {
        int c   = tid + h * 256;       // 0..511
        int row = c >> 2;
        int kb  = c & 3;
        size_t   go = (size_t)row * KDIM + k0 + kb * 8;
        uint32_t so = (uint32_t)(kb * 2048 + row * 16);
        CP_ASYNC16(sbase +          so, Ah + go);
        CP_ASYNC16(sbase +  8192u + so, Al + go);
        CP_ASYNC16(sbase + 16384u + so, Bh + go);
    }
}

// ---------------------------------------------------------------------------
// fp16 2-product mma GEMM: BM=128, BN=128, BK=32, 8 warps (4m x 2n).
// acc += Ah*Bh + Al*Bh   (A split fp16 hi/lo, B fp16)
// MODE 0: out = tanh(A@B)
// MODE 1: out = xl + x0*(A@B + bias)
// MODE 2: out = x0*(1 + A@B + bias), + fp16 hi/lo split of out
// ---------------------------------------------------------------------------
template<int MODE, int KDIM>
__global__ void __launch_bounds__(256, 2)
mma_gemm(const __half* __restrict__ Ahi, const __half* __restrict__ Alo,
         const __half* __restrict__ Bhi,
         const float* __restrict__ x0, const float* __restrict__ xl,
         const float* __restrict__ bias, float* __restrict__ out,
         __half* __restrict__ outhi, __half* __restrict__ outlo,
         int Nstride)
{
    constexpr int BK = 32, NK = KDIM / BK, NST = 3;
    constexpr uint32_t STAGE = 24576u;
    extern __shared__ char smem[];
    const uint32_t sbase = smem_u32(smem);

    const int tid  = threadIdx.x;
    const int wid  = tid >> 5;
    const int lane = tid & 31;
    const int wm   = wid & 3;
    const int wn   = wid >> 2;

    const __half* Ah = Ahi + (size_t)blockIdx.y * 128 * KDIM;
    const __half* Al = Alo + (size_t)blockIdx.y * 128 * KDIM;
    const __half* Bh = Bhi + (size_t)blockIdx.x * 128 * KDIM;

    float acc[2][8][4];
    #pragma unroll
    for (int a = 0; a < 2; a++)
        #pragma unroll
        for (int b = 0; b < 8; b++)
            #pragma unroll
            for (int c = 0; c < 4; c++) acc[a][b][c] = 0.0f;

    load_stage<KDIM>(sbase,         Ah, Al, Bh, 0,  tid); CP_COMMIT();
    load_stage<KDIM>(sbase + STAGE, Ah, Al, Bh, BK, tid); CP_COMMIT();

    const uint32_t arow16 = (uint32_t)((wm * 32 + (lane & 15)) * 16);
    const uint32_t asel   = (uint32_t)(lane >> 4) * 2048u;
    const uint32_t brow16 = (uint32_t)((wn * 64 + (lane & 7) + ((lane >> 4) << 3)) * 16);
    const uint32_t bsel   = (uint32_t)((lane >> 3) & 1) * 2048u;

    for (int i = 0; i < NK; i++) {
        CP_WAIT1();
        __syncthreads();
        if (i + 2 < NK)
            load_stage<KDIM>(sbase + (uint32_t)((i + 2) % NST) * STAGE,
                             Ah, Al, Bh, (i + 2) * BK, tid);
        CP_COMMIT();

        const uint32_t st = sbase + (uint32_t)(i % NST) * STAGE;
        #pragma unroll
        for (int kk = 0; kk < 2; kk++) {
            const uint32_t kboff = (uint32_t)kk * 4096u;
            uint32_t ah[2][4], al[2][4], bb[4][4];

            #pragma unroll
            for (int g = 0; g < 4; g++) {
                uint32_t bd = st + 16384u + kboff + bsel + brow16 + (uint32_t)g * 256u;
                LDSM_X4(bb[g][0], bb[g][1], bb[g][2], bb[g][3], bd);
            }
            #pragma unroll
            for (int mt = 0; mt < 2; mt++) {
                uint32_t ad = st + kboff + asel + arow16 + (uint32_t)mt * 256u;
                LDSM_X4(ah[mt][0], ah[mt][1], ah[mt][2], ah[mt][3], ad);
            }
            #pragma unroll
            for (int mt = 0; mt < 2; mt++)
                #pragma unroll
                for (int nt = 0; nt < 8; nt++) {
                    const int g = nt >> 1, hh = (nt & 1) * 2;
                    MMA_F16(acc[mt][nt], ah[mt], bb[g][hh], bb[g][hh + 1]);
                }
            #pragma unroll
            for (int mt = 0; mt < 2; mt++) {
                uint32_t ad = st + 8192u + kboff + asel + arow16 + (uint32_t)mt * 256u;
                LDSM_X4(al[mt][0], al[mt][1], al[mt][2], al[mt][3], ad);
            }
            #pragma unroll
            for (int mt = 0; mt < 2; mt++)
                #pragma unroll
                for (int nt = 0; nt < 8; nt++) {
                    const int g = nt >> 1, hh = (nt & 1) * 2;
                    MMA_F16(acc[mt][nt], al[mt], bb[g][hh], bb[g][hh + 1]);
                }
        }
    }

    const int r0    = lane >> 2;
    const int cpair = (lane & 3) * 2;
    #pragma unroll
    for (int mt = 0; mt < 2; mt++)
        #pragma unroll
        for (int nt = 0; nt < 8; nt++) {
            const int row = blockIdx.y * 128 + wm * 32 + mt * 16 + r0;
            const int col = blockIdx.x * 128 + wn * 64 + nt * 8 + cpair;
            #pragma unroll
            for (int h = 0; h < 2; h++) {
                const int rr = row + h * 8;
                const float v0 = acc[mt][nt][h * 2 + 0];
                const float v1 = acc[mt][nt][h * 2 + 1];
                const size_t o = (size_t)rr * Nstride + col;
                if (MODE == 0) {
                    float2 ov;
                    ov.x = tanhf(v0);
                    ov.y = tanhf(v1);
                    *(float2*)(out + o) = ov;
                } else if (MODE == 1) {
                    const float2 bv = *(const float2*)(bias + col);
                    const float2 xv = *(const float2*)(x0 + o);
                    const float2 lv = *(const float2*)(xl + o);
                    float2 ov;
                    ov.x = fmaf(xv.x, v0 + bv.x, lv.x);
                    ov.y = fmaf(xv.y, v1 + bv.y, lv.y);
                    *(float2*)(out + o) = ov;
                } else {
                    const float2 bv = *(const float2*)(bias + col);
                    const float2 xv = *(const float2*)(x0 + o);
                    float2 ov;
                    ov.x = xv.x * (1.0f + v0 + bv.x);
                    ov.y = xv.y * (1.0f + v1 + bv.y);
                    *(float2*)(out + o) = ov;
                    __half2 hv, lv2;
                    fp16_split(ov.x, hv.x, lv2.x);
                    fp16_split(ov.y, hv.y, lv2.y);
                    *(__half2*)(outhi + o) = hv;
                    *(__half2*)(outlo + o) = lv2;
                }
            }
        }
}

// ---------------------------------------------------------------------------
extern "C" void kernel_launch(void* const* d_in, const int* in_sizes, int n_in,
                              void* d_out, int out_size)
{
    const float* x     = (const float*)d_in[0];
    const float* U     = (const float*)d_in[1];
    const float* V     = (const float*)d_in[2];
    const float* C     = (const float*)d_in[3];
    const float* bias  = (const float*)d_in[4];
    const float* gateW = (const float*)d_in[5];
    float* out = (float*)d_out;

    __half *w1h, *w2h, *xh, *xlo, *zh, *zl;
    float *hbuf, *xlbuf, *gbuf;
    cudaGetSymbolAddress((void**)&w1h,   g_W1h);
    cudaGetSymbolAddress((void**)&w2h,   g_W2h);
    cudaGetSymbolAddress((void**)&xh,    g_Xhi);
    cudaGetSymbolAddress((void**)&xlo,   g_Xlo);
    cudaGetSymbolAddress((void**)&zh,    g_Zhi);
    cudaGetSymbolAddress((void**)&zl,    g_Zlo);
    cudaGetSymbolAddress((void**)&hbuf,  g_H);
    cudaGetSymbolAddress((void**)&xlbuf, g_Xl);
    cudaGetSymbolAddress((void**)&gbuf,  g_Gate);

    const int GEMM_SMEM = 3 * 24576;
    cudaFuncSetAttribute(mma_gemm<0, 1024>, cudaFuncAttributeMaxDynamicSharedMemorySize, GEMM_SMEM);
    cudaFuncSetAttribute(mma_gemm<1, 256>,  cudaFuncAttributeMaxDynamicSharedMemorySize, GEMM_SMEM);
    cudaFuncSetAttribute(mma_gemm<2, 256>,  cudaFuncAttributeMaxDynamicSharedMemorySize, GEMM_SMEM);

    repack_kernel<<<(L_NUM * N1 * D_DIM + 255) / 256, 256>>>(U, V);
    split_x_kernel<<<B_ROWS * D_DIM / 4 / 256, 256>>>(x);

    for (int i = 0; i < L_NUM; i++) {
        const float* xin = (i == 0) ? x : xlbuf;
        const size_t woff = (size_t)i * N1 * D_DIM;
        const float* Cl = C + (size_t)i * E_NUM * R_DIM * R_DIM;

        // GEMM1: H = tanh(X @ W1^T)   [16384 x 256], K = 1024
        mma_gemm<0, 1024><<<dim3(2, B_ROWS / 128), 256, GEMM_SMEM>>>(
            xh, xlo, w1h + woff,
            nullptr, nullptr, nullptr, hbuf, nullptr, nullptr, N1);

        gate_kernel<<<B_ROWS / 8, 256>>>(xin, gateW, gbuf);

        middle_kernel2<<<B_ROWS / 8, 256>>>(Cl, gbuf, hbuf, zh, zl);

        // GEMM2: out = xl + x0*(Z @ W2^T + bias)  [16384 x 1024], K = 256
        if (i == 0) {
            mma_gemm<2, 256><<<dim3(8, B_ROWS / 128), 256, GEMM_SMEM>>>(
                zh, zl, w2h + woff,
                x, nullptr, bias, xlbuf, xh, xlo, D_DIM);
        } else {
            mma_gemm<1, 256><<<dim3(8, B_ROWS / 128), 256, GEMM_SMEM>>>(
                zh, zl, w2h + woff,
                x, xin, bias + (size_t)i * D_DIM, out, nullptr, nullptr, D_DIM);
        }
    }
}

// round 7
// speedup vs baseline: 1.6681x; 1.3206x over previous
#include <cuda_runtime.h>
#include <cuda_fp16.h>
#include <math.h>
#include <stdint.h>

#define B_ROWS 16384
#define D_DIM  1024
#define R_DIM  64
#define E_NUM  4
#define L_NUM  2
#define N1     256   // E * R

// ---------------------------------------------------------------------------
// Device scratch
// ---------------------------------------------------------------------------
__device__ __half g_W1h[L_NUM * N1 * D_DIM];   // [L][n=e*64+r][k=d]  fp16(V)
__device__ __half g_W2h[L_NUM * D_DIM * N1];   // [L][n=d][k=e*64+r]  fp16(U)
__device__ __half g_Xh [B_ROWS * D_DIM];       // fp16(x_l)
__device__ __half g_Zh [B_ROWS * N1];          // fp16(Z)
__device__ float g_H   [B_ROWS * N1];
__device__ float g_Xl  [B_ROWS * D_DIM];
__device__ float g_Gate[B_ROWS * E_NUM];

// ---------------------------------------------------------------------------
// Helpers
// ---------------------------------------------------------------------------
__device__ __forceinline__ uint32_t smem_u32(const void* p) {
    uint32_t a;
    asm("{ .reg .u64 t; cvta.to.shared.u64 t, %1; cvt.u32.u64 %0, t; }"
        : "=r"(a) : "l"(p));
    return a;
}

#define CP_ASYNC16(dst, src) \
    asm volatile("cp.async.cg.shared.global [%0], [%1], 16;" :: "r"(dst), "l"(src))
#define CP_COMMIT() asm volatile("cp.async.commit_group;" ::: "memory")
#define CP_WAIT1()  asm volatile("cp.async.wait_group 1;" ::: "memory")

#define LDSM_X4(r0, r1, r2, r3, addr) \
    asm volatile("ldmatrix.sync.aligned.m8n8.x4.shared.b16 {%0,%1,%2,%3}, [%4];" \
        : "=r"(r0), "=r"(r1), "=r"(r2), "=r"(r3) : "r"(addr))

#define MMA_F16(d, a, b0, b1) \
    asm volatile("mma.sync.aligned.m16n8k16.row.col.f32.f16.f16.f32 " \
        "{%0,%1,%2,%3}, {%4,%5,%6,%7}, {%8,%9}, {%0,%1,%2,%3};" \
        : "+f"((d)[0]), "+f"((d)[1]), "+f"((d)[2]), "+f"((d)[3]) \
        : "r"((a)[0]), "r"((a)[1]), "r"((a)[2]), "r"((a)[3]), "r"(b0), "r"(b1))

// ---------------------------------------------------------------------------
// Weight repack (fp16)
// ---------------------------------------------------------------------------
__global__ void repack_kernel(const float* __restrict__ U, const float* __restrict__ V) {
    int idx = blockIdx.x * blockDim.x + threadIdx.x;
    const int per = N1 * D_DIM;
    if (idx >= L_NUM * per) return;
    int i   = idx / per;
    int rem = idx - i * per;
    {   // W1[n][k] = V[i, e=n>>6, d=k, r=n&63]
        int n = rem / D_DIM, k = rem - (rem / D_DIM) * D_DIM;
        float v = V[(((size_t)i * E_NUM + (n >> 6)) * D_DIM + k) * R_DIM + (n & 63)];
        g_W1h[idx] = __float2half_rn(v);
    }
    {   // W2[d][k2] = U[i, e=k2>>6, d, r=k2&63]
        int d = rem / N1, k2 = rem - (rem / N1) * N1;
        float u = U[(((size_t)i * E_NUM + (k2 >> 6)) * D_DIM + d) * R_DIM + (k2 & 63)];
        g_W2h[(size_t)i * D_DIM * N1 + rem] = __float2half_rn(u);
    }
}

__global__ void convert_x_kernel(const float* __restrict__ x) {
    int i = (blockIdx.x * 256 + threadIdx.x) * 4;
    float4 v = *(const float4*)(x + i);
    __half2 h01, h23;
    h01.x = __float2half_rn(v.x); h01.y = __float2half_rn(v.y);
    h23.x = __float2half_rn(v.z); h23.y = __float2half_rn(v.w);
    *(__half2*)(g_Xh + i)     = h01;
    *(__half2*)(g_Xh + i + 2) = h23;
}

// ---------------------------------------------------------------------------
// Gate kernel: warp-per-row logits + softmax -> g_Gate[b][4]
// ---------------------------------------------------------------------------
__global__ void __launch_bounds__(256)
gate_kernel(const float* __restrict__ X, const float* __restrict__ gateW,
            float* __restrict__ gate)
{
    __shared__ float sG[E_NUM * D_DIM];
    const int tid = threadIdx.x;
    #pragma unroll
    for (int i = tid * 4; i < E_NUM * D_DIM; i += 1024)
        *(float4*)(sG + i) = *(const float4*)(gateW + i);
    __syncthreads();

    const int warp = tid >> 5, lane = tid & 31;
    const int b = blockIdx.x * 8 + warp;
    const float* xr = X + (size_t)b * D_DIM;

    float a0 = 0.f, a1 = 0.f, a2 = 0.f, a3 = 0.f;
    #pragma unroll
    for (int j = 0; j < 8; j++) {
        const int off = lane * 4 + j * 128;
        float4 xv = *(const float4*)(xr + off);
        float4 g0 = *(const float4*)(sG + 0 * D_DIM + off);
        float4 g1 = *(const float4*)(sG + 1 * D_DIM + off);
        float4 g2 = *(const float4*)(sG + 2 * D_DIM + off);
        float4 g3 = *(const float4*)(sG + 3 * D_DIM + off);
        a0 += xv.x * g0.x + xv.y * g0.y + xv.z * g0.z + xv.w * g0.w;
        a1 += xv.x * g1.x + xv.y * g1.y + xv.z * g1.z + xv.w * g1.w;
        a2 += xv.x * g2.x + xv.y * g2.y + xv.z * g2.z + xv.w * g2.w;
        a3 += xv.x * g3.x + xv.y * g3.y + xv.z * g3.z + xv.w * g3.w;
    }
    #pragma unroll
    for (int o = 16; o > 0; o >>= 1) {
        a0 += __shfl_xor_sync(0xffffffffu, a0, o);
        a1 += __shfl_xor_sync(0xffffffffu, a1, o);
        a2 += __shfl_xor_sync(0xffffffffu, a2, o);
        a3 += __shfl_xor_sync(0xffffffffu, a3, o);
    }
    float mx = fmaxf(fmaxf(a0, a1), fmaxf(a2, a3));
    float e0 = expf(a0 - mx), e1 = expf(a1 - mx), e2 = expf(a2 - mx), e3 = expf(a3 - mx);
    float inv = 1.0f / (e0 + e1 + e2 + e3);
    if (lane < 4) {
        float v = (lane == 0) ? e0 : (lane == 1) ? e1 : (lane == 2) ? e2 : e3;
        gate[b * 4 + lane] = v * inv;
    }
}

// ---------------------------------------------------------------------------
// Middle v2: register-resident C. Thread tid owns C row n=tid (64 regs).
// ---------------------------------------------------------------------------
__global__ void __launch_bounds__(256)
middle_kernel2(const float* __restrict__ C, const float* __restrict__ gate,
               const float* __restrict__ H, __half* __restrict__ Zh)
{
    __shared__ float sH[8][N1];
    const int tid = threadIdx.x;
    const int b0  = blockIdx.x * 8;
    const int e   = tid >> 6;

    float Creg[64];
    {
        const float* crow = C + (size_t)tid * 64;
        #pragma unroll
        for (int q = 0; q < 64; q += 4) {
            float4 v = *(const float4*)(crow + q);
            Creg[q + 0] = v.x; Creg[q + 1] = v.y;
            Creg[q + 2] = v.z; Creg[q + 3] = v.w;
        }
    }
    {
        const int row = tid >> 5;
        const int c   = (tid & 31) * 8;
        *(float4*)(&sH[row][c])     = *(const float4*)(H + (size_t)(b0 + row) * N1 + c);
        *(float4*)(&sH[row][c + 4]) = *(const float4*)(H + (size_t)(b0 + row) * N1 + c + 4);
    }
    __syncthreads();

    #pragma unroll
    for (int r = 0; r < 8; r++) {
        const float* hseg = &sH[r][e * 64];
        float acc = 0.0f;
        #pragma unroll
        for (int q = 0; q < 64; q++)
            acc = fmaf(Creg[q], hseg[q], acc);
        const float g = gate[(b0 + r) * 4 + e];
        Zh[(size_t)(b0 + r) * N1 + tid] = __float2half_rn(g * tanhf(acc));
    }
}

// ---------------------------------------------------------------------------
// Stage loader: 2 arrays (A, B), each 128 rows x 32 k (fp16) = 8KB.
// Panel layout: k-chunk kb (8 k) -> 128 rows x 16B at offset kb*2048 + row*16.
// ---------------------------------------------------------------------------
template<int KDIM>
__device__ __forceinline__ void load_stage(
    uint32_t sbase,
    const __half* __restrict__ A, const __half* __restrict__ B,
    int k0, int tid)
{
    #pragma unroll
    for (int h = 0; h < 2; h++) {
        int c   = tid + h * 256;       // 0..511
        int row = c >> 2;
        int kb  = c & 3;
        size_t   go = (size_t)row * KDIM + k0 + kb * 8;
        uint32_t so = (uint32_t)(kb * 2048 + row * 16);
        CP_ASYNC16(sbase +         so, A + go);
        CP_ASYNC16(sbase + 8192u + so, B + go);
    }
}

// ---------------------------------------------------------------------------
// fp16 single-product mma GEMM: BM=128, BN=128, BK=32, 8 warps (4m x 2n).
// MODE 0: out = tanh(A@B)
// MODE 1: out = xl + x0*(A@B + bias)
// MODE 2: out = x0*(1 + A@B + bias), + fp16 copy of out
// ---------------------------------------------------------------------------
template<int MODE, int KDIM>
__global__ void __launch_bounds__(256, 2)
mma_gemm(const __half* __restrict__ Ag, const __half* __restrict__ Bg,
         const float* __restrict__ x0, const float* __restrict__ xl,
         const float* __restrict__ bias, float* __restrict__ out,
         __half* __restrict__ outh, int Nstride)
{
    constexpr int BK = 32, NK = KDIM / BK, NST = 3;
    constexpr uint32_t STAGE = 16384u;
    extern __shared__ char smem[];
    const uint32_t sbase = smem_u32(smem);

    const int tid  = threadIdx.x;
    const int wid  = tid >> 5;
    const int lane = tid & 31;
    const int wm   = wid & 3;
    const int wn   = wid >> 2;

    const __half* A = Ag + (size_t)blockIdx.y * 128 * KDIM;
    const __half* B = Bg + (size_t)blockIdx.x * 128 * KDIM;

    float acc[2][8][4];
    #pragma unroll
    for (int a = 0; a < 2; a++)
        #pragma unroll
        for (int b = 0; b < 8; b++)
            #pragma unroll
            for (int c = 0; c < 4; c++) acc[a][b][c] = 0.0f;

    load_stage<KDIM>(sbase,         A, B, 0,  tid); CP_COMMIT();
    load_stage<KDIM>(sbase + STAGE, A, B, BK, tid); CP_COMMIT();

    const uint32_t arow16 = (uint32_t)((wm * 32 + (lane & 15)) * 16);
    const uint32_t asel   = (uint32_t)(lane >> 4) * 2048u;
    const uint32_t brow16 = (uint32_t)((wn * 64 + (lane & 7) + ((lane >> 4) << 3)) * 16);
    const uint32_t bsel   = (uint32_t)((lane >> 3) & 1) * 2048u;

    for (int i = 0; i < NK; i++) {
        CP_WAIT1();
        __syncthreads();
        if (i + 2 < NK)
            load_stage<KDIM>(sbase + (uint32_t)((i + 2) % NST) * STAGE,
                             A, B, (i + 2) * BK, tid);
        CP_COMMIT();

        const uint32_t st = sbase + (uint32_t)(i % NST) * STAGE;
        #pragma unroll
        for (int kk = 0; kk < 2; kk++) {
            const uint32_t kboff = (uint32_t)kk * 4096u;
            uint32_t ah[2][4], bb[4][4];

            #pragma unroll
            for (int g = 0; g < 4; g++) {
                uint32_t bd = st + 8192u + kboff + bsel + brow16 + (uint32_t)g * 256u;
                LDSM_X4(bb[g][0], bb[g][1], bb[g][2], bb[g][3], bd);
            }
            #pragma unroll
            for (int mt = 0; mt < 2; mt++) {
                uint32_t ad = st + kboff + asel + arow16 + (uint32_t)mt * 256u;
                LDSM_X4(ah[mt][0], ah[mt][1], ah[mt][2], ah[mt][3], ad);
            }
            #pragma unroll
            for (int mt = 0; mt < 2; mt++)
                #pragma unroll
                for (int nt = 0; nt < 8; nt++) {
                    const int g = nt >> 1, hh = (nt & 1) * 2;
                    MMA_F16(acc[mt][nt], ah[mt], bb[g][hh], bb[g][hh + 1]);
                }
        }
    }

    const int r0    = lane >> 2;
    const int cpair = (lane & 3) * 2;
    #pragma unroll
    for (int mt = 0; mt < 2; mt++)
        #pragma unroll
        for (int nt = 0; nt < 8; nt++) {
            const int row = blockIdx.y * 128 + wm * 32 + mt * 16 + r0;
            const int col = blockIdx.x * 128 + wn * 64 + nt * 8 + cpair;
            #pragma unroll
            for (int h = 0; h < 2; h++) {
                const int rr = row + h * 8;
                const float v0 = acc[mt][nt][h * 2 + 0];
                const float v1 = acc[mt][nt][h * 2 + 1];
                const size_t o = (size_t)rr * Nstride + col;
                if (MODE == 0) {
                    float2 ov;
                    ov.x = tanhf(v0);
                    ov.y = tanhf(v1);
                    *(float2*)(out + o) = ov;
                } else if (MODE == 1) {
                    const float2 bv = *(const float2*)(bias + col);
                    const float2 xv = *(const float2*)(x0 + o);
                    const float2 lv = *(const float2*)(xl + o);
                    float2 ov;
                    ov.x = fmaf(xv.x, v0 + bv.x, lv.x);
                    ov.y = fmaf(xv.y, v1 + bv.y, lv.y);
                    *(float2*)(out + o) = ov;
                } else {
                    const float2 bv = *(const float2*)(bias + col);
                    const float2 xv = *(const float2*)(x0 + o);
                    float2 ov;
                    ov.x = xv.x * (1.0f + v0 + bv.x);
                    ov.y = xv.y * (1.0f + v1 + bv.y);
                    *(float2*)(out + o) = ov;
                    __half2 hv;
                    hv.x = __float2half_rn(ov.x);
                    hv.y = __float2half_rn(ov.y);
                    *(__half2*)(outh + o) = hv;
                }
            }
        }
}

// ---------------------------------------------------------------------------
extern "C" void kernel_launch(void* const* d_in, const int* in_sizes, int n_in,
                              void* d_out, int out_size)
{
    const float* x     = (const float*)d_in[0];
    const float* U     = (const float*)d_in[1];
    const float* V     = (const float*)d_in[2];
    const float* C     = (const float*)d_in[3];
    const float* bias  = (const float*)d_in[4];
    const float* gateW = (const float*)d_in[5];
    float* out = (float*)d_out;

    __half *w1h, *w2h, *xh, *zh;
    float *hbuf, *xlbuf, *gbuf;
    cudaGetSymbolAddress((void**)&w1h,   g_W1h);
    cudaGetSymbolAddress((void**)&w2h,   g_W2h);
    cudaGetSymbolAddress((void**)&xh,    g_Xh);
    cudaGetSymbolAddress((void**)&zh,    g_Zh);
    cudaGetSymbolAddress((void**)&hbuf,  g_H);
    cudaGetSymbolAddress((void**)&xlbuf, g_Xl);
    cudaGetSymbolAddress((void**)&gbuf,  g_Gate);

    const int GEMM_SMEM = 3 * 16384;
    cudaFuncSetAttribute(mma_gemm<0, 1024>, cudaFuncAttributeMaxDynamicSharedMemorySize, GEMM_SMEM);
    cudaFuncSetAttribute(mma_gemm<1, 256>,  cudaFuncAttributeMaxDynamicSharedMemorySize, GEMM_SMEM);
    cudaFuncSetAttribute(mma_gemm<2, 256>,  cudaFuncAttributeMaxDynamicSharedMemorySize, GEMM_SMEM);

    repack_kernel<<<(L_NUM * N1 * D_DIM + 255) / 256, 256>>>(U, V);
    convert_x_kernel<<<B_ROWS * D_DIM / 4 / 256, 256>>>(x);

    for (int i = 0; i < L_NUM; i++) {
        const float* xin = (i == 0) ? x : xlbuf;
        const size_t woff = (size_t)i * N1 * D_DIM;
        const float* Cl = C + (size_t)i * E_NUM * R_DIM * R_DIM;

        // GEMM1: H = tanh(X @ W1^T)   [16384 x 256], K = 1024
        mma_gemm<0, 1024><<<dim3(2, B_ROWS / 128), 256, GEMM_SMEM>>>(
            xh, w1h + woff, nullptr, nullptr, nullptr, hbuf, nullptr, N1);

        gate_kernel<<<B_ROWS / 8, 256>>>(xin, gateW, gbuf);

        middle_kernel2<<<B_ROWS / 8, 256>>>(Cl, gbuf, hbuf, zh);

        // GEMM2: out = xl + x0*(Z @ W2^T + bias)  [16384 x 1024], K = 256
        if (i == 0) {
            mma_gemm<2, 256><<<dim3(8, B_ROWS / 128), 256, GEMM_SMEM>>>(
                zh, w2h + woff, x, nullptr, bias, xlbuf, xh, D_DIM);
        } else {
            mma_gemm<1, 256><<<dim3(8, B_ROWS / 128), 256, GEMM_SMEM>>>(
                zh, w2h + woff, x, xin, bias + (size_t)i * D_DIM, out, nullptr, D_DIM);
        }
    }
}